// round 4
// baseline (speedup 1.0000x reference)
#include <cuda_runtime.h>
#include <cstdint>

#define B          64
#define CROP       64
#define MAXN       196
#define KNBR       6
#define NSCORE     (3*CROP*CROP)        // 12288
#define THREADS    256
#define WB         247
#define WS         18

// output layout (f32, concatenated flattened tuple)
#define O_NODES 0
#define O_EI    62720
#define O_EF    213248
#define O_BI    439040
#define O_NV    451584
#define O_EV    464128
#define N_EDGE_TOT 75264                // B*196*6

__device__ __forceinline__ float score_of(float r) {
    float m = fabsf(r);
    return (m > 0.1f) ? m : -1.0f;
}
__device__ __forceinline__ unsigned enc_f(float s) {
    unsigned b = __float_as_uint(s);
    return (b & 0x80000000u) ? ~b : (b | 0x80000000u);
}

__global__ void __launch_bounds__(THREADS, 1)
retinal_kernel(const float* __restrict__ img,
               const float* __restrict__ w1,
               const float* __restrict__ w2,
               const float* __restrict__ w3,
               float* __restrict__ out)
{
    extern __shared__ unsigned char dsm[];
    float* s_resp = (float*)dsm;                 // 12288
    float* s_gray = s_resp + NSCORE;             // 4096
    float* s_win  = s_gray + CROP*CROP;          // 3*18*18 = 972
    float* s_w    = s_win + 3*WS*WS;             // 115
    unsigned long long* s_sel =
        (unsigned long long*)(((uintptr_t)(s_w + 115) + 15) & ~(uintptr_t)15); // 256
    float* s_nx   = (float*)(s_sel + 256);       // 196
    float* s_ny   = s_nx + MAXN;                 // 196
    int*   s_val  = (int*)(s_ny + MAXN);         // 196

    __shared__ unsigned s_hist[256];
    __shared__ unsigned s_pref;
    __shared__ int s_rem, s_nsel, s_tiebase;
    __shared__ int s_wcnt[8];

    const int b = blockIdx.x;
    const int t = threadIdx.x;

    // XLA algebraic-simplifier constants:
    const float REC63x2 = __uint_as_float(0x3D020821u);  // f32(1/63) * 2
    const float REC3    = __uint_as_float(0x3EAAAAABu);  // f32(1/3)

    // ---- load DoG weights ----
    if (t < 9)          s_w[t]      = w1[t];
    if (t < 25)         s_w[9 + t]  = w2[t];
    if (t < 81)         s_w[34 + t] = w3[t];

    // ---- load 18x18x3 source window ----
    for (int i = t; i < 3*WS*WS; i += THREADS) {
        int c = i / (WS*WS);
        int r = (i % (WS*WS)) / WS;
        int x = i % WS;
        s_win[i] = img[(((size_t)b*3 + c)*512 + (WB + r))*512 + (WB + x)];
    }
    __syncthreads();

    // ---- crop (bilinear) + gray mean ----
    for (int p = t; p < CROP*CROP; p += THREADS) {
        int iy = p >> 6, ix = p & 63;
        // (i+0.5)/32 is exact (power-of-two recip); px quarter-steps exact
        float bx = __fsub_rn(__fmul_rn((float)ix + 0.5f, 0.03125f), 1.0f);
        float by = __fsub_rn(__fmul_rn((float)iy + 0.5f, 0.03125f), 1.0f);
        float px = __fsub_rn(__fmul_rn(__fadd_rn(__fmul_rn(bx, 0.03125f), 1.0f), 256.0f), 0.5f);
        float py = __fsub_rn(__fmul_rn(__fadd_rn(__fmul_rn(by, 0.03125f), 1.0f), 256.0f), 0.5f);
        int ix0 = (int)floorf(px), iy0 = (int)floorf(py);
        float fx = __fsub_rn(px, (float)ix0);
        float fy = __fsub_rn(py, (float)iy0);
        float wx0 = __fsub_rn(1.0f, fx);
        float wy0 = __fsub_rn(1.0f, fy);
        int lx0 = ix0 - WB, ly0 = iy0 - WB;
        float sum = 0.0f;
        #pragma unroll
        for (int c = 0; c < 3; c++) {
            const float* wc = s_win + c*WS*WS;
            float v00 = wc[ly0*WS + lx0],     v01 = wc[ly0*WS + lx0 + 1];
            float v10 = wc[(ly0+1)*WS + lx0], v11 = wc[(ly0+1)*WS + lx0 + 1];
            float tx0 = __fadd_rn(__fmul_rn(v00, wx0), __fmul_rn(v01, fx));
            float tx1 = __fadd_rn(__fmul_rn(v10, wx0), __fmul_rn(v11, fx));
            float v   = __fadd_rn(__fmul_rn(tx0, wy0), __fmul_rn(tx1, fy));
            sum = __fadd_rn(sum, v);
        }
        // mean lowered by XLA as sum * (1/3)
        s_gray[p] = __fmul_rn(sum, REC3);
    }
    __syncthreads();

    // ---- 3 DoG convs (SAME, zero pad) ----
    for (int o = t; o < NSCORE; o += THREADS) {
        int ch = o >> 12;
        int p = o & 4095;
        int y = p >> 6, x = p & 63;
        float acc = 0.0f;
        int k, pad, wb;
        if (ch == 0)      { k = 3; pad = 1; wb = 0; }
        else if (ch == 1) { k = 5; pad = 2; wb = 9; }
        else              { k = 9; pad = 4; wb = 34; }
        for (int dy = 0; dy < k; dy++) {
            int yy = y + dy - pad;
            if ((unsigned)yy >= 64u) continue;
            const float* gr = s_gray + yy*64;
            const float* wr = s_w + wb + dy*k;
            for (int dx = 0; dx < k; dx++) {
                int xx = x + dx - pad;
                if ((unsigned)xx >= 64u) continue;
                acc = fmaf(gr[xx], wr[dx], acc);
            }
        }
        s_resp[o] = acc;
    }
    __syncthreads();

    // ---- radix select: value of 196th-largest encoded score ----
    if (t == 0) { s_pref = 0; s_rem = MAXN; }
    __syncthreads();
    for (int pass = 0; pass < 4; pass++) {
        int shift = 24 - 8*pass;
        if (t < 256) s_hist[t] = 0;
        __syncthreads();
        unsigned pref = s_pref;
        for (int i = t; i < NSCORE; i += THREADS) {
            unsigned u = enc_f(score_of(s_resp[i]));
            bool ok = (pass == 0) || (((u ^ pref) >> (shift + 8)) == 0);
            if (ok) atomicAdd(&s_hist[(u >> shift) & 0xFFu], 1u);
        }
        __syncthreads();
        if (t == 0) {
            int rem = s_rem;
            int d = 255;
            for (; d >= 0; d--) {
                int c = (int)s_hist[d];
                if (rem <= c) break;
                rem -= c;
            }
            if (d < 0) d = 0;  // safety, unreachable by invariant
            s_pref = s_pref | ((unsigned)d << shift);
            s_rem  = rem;
        }
        __syncthreads();
    }
    const unsigned u_t = s_pref;
    const int ktie = s_rem;

    // ---- collect strictly-greater entries (unordered; sort fixes order) ----
    if (t == 0) { s_nsel = 0; s_tiebase = 0; }
    __syncthreads();
    for (int i = t; i < NSCORE; i += THREADS) {
        unsigned u = enc_f(score_of(s_resp[i]));
        if (u > u_t) {
            int pos = atomicAdd(&s_nsel, 1);
            s_sel[pos] = (((unsigned long long)u) << 32) | (unsigned)(~(unsigned)i);
        }
    }
    __syncthreads();
    const int cG = s_nsel;     // == 196 - ktie by radix invariant

    // ---- collect first ktie tie entries in ascending-index order ----
    for (int base = 0; base < NSCORE; base += THREADS) {
        int i = base + t;
        unsigned u = enc_f(score_of(s_resp[i]));
        bool pred = (u == u_t);
        unsigned bal = __ballot_sync(0xffffffffu, pred);
        int lane = t & 31, wp = t >> 5;
        if (lane == 0) s_wcnt[wp] = __popc(bal);
        __syncthreads();
        int off = 0, tot = 0;
        #pragma unroll
        for (int q = 0; q < 8; q++) {
            int c = s_wcnt[q];
            if (q < wp) off += c;
            tot += c;
        }
        int rank = s_tiebase + off + __popc(bal & ((1u << lane) - 1u));
        if (pred && rank < ktie)
            s_sel[cG + rank] = (((unsigned long long)u) << 32) | (unsigned)(~(unsigned)i);
        __syncthreads();
        if (t == 0) s_tiebase += tot;
        __syncthreads();
        if (s_tiebase >= ktie) break;
    }
    if (t >= MAXN) s_sel[t] = 0ULL;   // pad for sort
    __syncthreads();

    // ---- bitonic sort 256 keys descending -> top-196 in JAX top_k order ----
    for (int kk = 2; kk <= 256; kk <<= 1) {
        for (int j = kk >> 1; j > 0; j >>= 1) {
            __syncthreads();
            int ixj = t ^ j;
            if (ixj > t) {
                unsigned long long a = s_sel[t], c = s_sel[ixj];
                bool descend = ((t & kk) == 0);
                if (descend ? (a < c) : (a > c)) { s_sel[t] = c; s_sel[ixj] = a; }
            }
        }
    }
    __syncthreads();

    // ---- node features ----
    const float DIST_T = (float)(4.05 / 4.2);
    if (t < MAXN) {
        unsigned long long key = s_sel[t];
        unsigned idx = ~((unsigned)key);
        float rv = s_resp[idx];
        float mag = fabsf(rv);
        bool valid = (mag > 0.1f);
        int c  = idx >> 12;
        int rem = idx & 4095;
        int yi = rem >> 6, xi = rem & 63;
        // XLA: xi/63*2 - 1  ->  xi * f32(2*recip(63)) - 1   (div->recip-mul rewrite)
        float xc = __fsub_rn(__fmul_rn((float)xi, REC63x2), 1.0f);
        float yc = __fsub_rn(__fmul_rn((float)yi, REC63x2), 1.0f);
        float ecc = __fsqrt_rn(__fadd_rn(__fmul_rn(xc, xc), __fmul_rn(yc, yc)));
        float pol = (rv > 0.0f) ? 1.0f : ((rv < 0.0f) ? -1.0f : 0.0f);
        float vf = valid ? 1.0f : 0.0f;
        float* nrow = out + O_NODES + ((size_t)b*MAXN + t)*5;
        nrow[0] = xc * vf;
        nrow[1] = yc * vf;
        nrow[2] = pol * vf;
        nrow[3] = (float)c * vf;
        nrow[4] = ecc * vf;
        s_nx[t] = xc * vf;
        s_ny[t] = yc * vf;
        s_val[t] = valid ? 1 : 0;
        out[O_NV + b*MAXN + t] = vf;
        out[O_BI + b*MAXN + t] = (float)b;
    }
    __syncthreads();

    // ---- 6-NN + edges ----
    if (t < MAXN) {
        float xs = s_nx[t], ys = s_ny[t];
        int sv = s_val[t];
        unsigned long long nn[KNBR];
        #pragma unroll
        for (int q = 0; q < KNBR; q++) nn[q] = 0xFFFFFFFFFFFFFFFFULL;
        for (int j = 0; j < MAXN; j++) {
            float d;
            if (sv && s_val[j] && j != t) {
                float dx = __fsub_rn(xs, s_nx[j]);
                float dy = __fsub_rn(ys, s_ny[j]);
                float s2 = __fadd_rn(__fmul_rn(dx, dx), __fmul_rn(dy, dy));
                d = (s2 > 0.0f) ? __fsqrt_rn(s2) : 0.0f;
            } else {
                d = 1000000000.0f;
            }
            unsigned long long key =
                (((unsigned long long)__float_as_uint(d)) << 32) | (unsigned)j;
            if (key < nn[KNBR-1]) {
                nn[KNBR-1] = key;
                #pragma unroll
                for (int q = KNBR-1; q > 0; q--) {
                    if (nn[q] < nn[q-1]) {
                        unsigned long long tmp = nn[q]; nn[q] = nn[q-1]; nn[q-1] = tmp;
                    }
                }
            }
        }
        #pragma unroll
        for (int q = 0; q < KNBR; q++) {
            unsigned jd = (unsigned)nn[q];
            float d = __uint_as_float((unsigned)(nn[q] >> 32));
            bool ev = (d < DIST_T) && (sv != 0);
            float evf = ev ? 1.0f : 0.0f;
            float dx = __fsub_rn(s_nx[jd], xs);
            float dy = __fsub_rn(s_ny[jd], ys);
            float s2 = __fadd_rn(__fmul_rn(dx, dx), __fmul_rn(dy, dy));
            float cd = (s2 > 0.0f) ? __fsqrt_rn(s2) : 0.0f;
            size_t e = ((size_t)b*MAXN + t)*KNBR + q;
            out[O_EI + e]              = ev ? (float)(b*MAXN + t)  : 0.0f;
            out[O_EI + N_EDGE_TOT + e] = ev ? (float)(b*MAXN + jd) : 0.0f;
            out[O_EF + e*3 + 0] = dx * evf;
            out[O_EF + e*3 + 1] = dy * evf;
            out[O_EF + e*3 + 2] = cd * evf;
            out[O_EV + e] = evf;
        }
    }
}

extern "C" void kernel_launch(void* const* d_in, const int* in_sizes, int n_in,
                              void* d_out, int out_size)
{
    const float* img = (const float*)d_in[0];
    const float* w1  = (const float*)d_in[1];
    const float* w2  = (const float*)d_in[2];
    const float* w3  = (const float*)d_in[3];
    float* out = (float*)d_out;

    const int smem_bytes = 78 * 1024;
    cudaFuncSetAttribute(retinal_kernel,
                         cudaFuncAttributeMaxDynamicSharedMemorySize, smem_bytes);
    retinal_kernel<<<B, THREADS, smem_bytes>>>(img, w1, w2, w3, out);
}

// round 5
// speedup vs baseline: 1.7371x; 1.7371x over previous
#include <cuda_runtime.h>
#include <cstdint>

#define B          64
#define CROP       64
#define MAXN       196
#define KNBR       6
#define NSCORE     (3*CROP*CROP)        // 12288
#define WB         247
#define WS         18
#define TB         256                  // conv kernel threads
#define TC         512                  // graph kernel threads

// output layout (f32, concatenated flattened tuple)
#define O_NODES 0
#define O_EI    62720
#define O_EF    213248
#define O_BI    439040
#define O_NV    451584
#define O_EV    464128
#define N_EDGE_TOT 75264                // B*196*6

__device__ float g_resp[B * NSCORE];    // 3 MB scratch

__device__ __forceinline__ float score_of(float r) {
    float m = fabsf(r);
    return (m > 0.1f) ? m : -1.0f;
}
__device__ __forceinline__ unsigned enc_f(float s) {
    unsigned b = __float_as_uint(s);
    return (b & 0x80000000u) ? ~b : (b | 0x80000000u);
}

// ============================================================
// Kernel 1: crop + gray + DoG convs.  grid = (64 batches, 8 slices)
//   slice 0       -> ch0 (k=3),  outputs [0,4096)
//   slice 1..2    -> ch1 (k=5),  halves of 4096
//   slice 3..7    -> ch2 (k=9),  fifths (820 each, last 816)
// ============================================================
__global__ void __launch_bounds__(TB)
conv_kernel(const float* __restrict__ img,
            const float* __restrict__ w1,
            const float* __restrict__ w2,
            const float* __restrict__ w3)
{
    __shared__ float s_win[3*WS*WS];
    __shared__ float s_w[115];
    __shared__ float s_gray[CROP*CROP];

    const int b = blockIdx.x;
    const int slice = blockIdx.y;
    const int t = threadIdx.x;
    const float REC3 = __uint_as_float(0x3EAAAAABu);  // f32(1/3)

    if (t < 9)  s_w[t]      = w1[t];
    if (t < 25) s_w[9 + t]  = w2[t];
    if (t < 81) s_w[34 + t] = w3[t];
    for (int i = t; i < 3*WS*WS; i += TB) {
        int c = i / (WS*WS);
        int r = (i % (WS*WS)) / WS;
        int x = i % WS;
        s_win[i] = img[(((size_t)b*3 + c)*512 + (WB + r))*512 + (WB + x)];
    }
    __syncthreads();

    // crop (bilinear) + gray mean — identical arithmetic to the passing kernel
    for (int p = t; p < CROP*CROP; p += TB) {
        int iy = p >> 6, ix = p & 63;
        float bx = __fsub_rn(__fmul_rn((float)ix + 0.5f, 0.03125f), 1.0f);
        float by = __fsub_rn(__fmul_rn((float)iy + 0.5f, 0.03125f), 1.0f);
        float px = __fsub_rn(__fmul_rn(__fadd_rn(__fmul_rn(bx, 0.03125f), 1.0f), 256.0f), 0.5f);
        float py = __fsub_rn(__fmul_rn(__fadd_rn(__fmul_rn(by, 0.03125f), 1.0f), 256.0f), 0.5f);
        int ix0 = (int)floorf(px), iy0 = (int)floorf(py);
        float fx = __fsub_rn(px, (float)ix0);
        float fy = __fsub_rn(py, (float)iy0);
        float wx0 = __fsub_rn(1.0f, fx);
        float wy0 = __fsub_rn(1.0f, fy);
        int lx0 = ix0 - WB, ly0 = iy0 - WB;
        float sum = 0.0f;
        #pragma unroll
        for (int c = 0; c < 3; c++) {
            const float* wc = s_win + c*WS*WS;
            float v00 = wc[ly0*WS + lx0],     v01 = wc[ly0*WS + lx0 + 1];
            float v10 = wc[(ly0+1)*WS + lx0], v11 = wc[(ly0+1)*WS + lx0 + 1];
            float tx0 = __fadd_rn(__fmul_rn(v00, wx0), __fmul_rn(v01, fx));
            float tx1 = __fadd_rn(__fmul_rn(v10, wx0), __fmul_rn(v11, fx));
            float v   = __fadd_rn(__fmul_rn(tx0, wy0), __fmul_rn(tx1, fy));
            sum = __fadd_rn(sum, v);
        }
        s_gray[p] = __fmul_rn(sum, REC3);
    }
    __syncthreads();

    int ch, obeg, oend;
    if (slice == 0)      { ch = 0; obeg = 0;                 oend = 4096; }
    else if (slice <= 2) { ch = 1; obeg = (slice-1)*2048;    oend = obeg + 2048; }
    else                 { ch = 2; obeg = (slice-3)*820;     oend = min(4096, obeg + 820); }

    int k, pad, wb;
    if (ch == 0)      { k = 3; pad = 1; wb = 0; }
    else if (ch == 1) { k = 5; pad = 2; wb = 9; }
    else              { k = 9; pad = 4; wb = 34; }

    float* dst = g_resp + (size_t)b*NSCORE + ch*4096;
    for (int p = obeg + t; p < oend; p += TB) {
        int y = p >> 6, x = p & 63;
        float acc = 0.0f;
        for (int dy = 0; dy < k; dy++) {
            int yy = y + dy - pad;
            if ((unsigned)yy >= 64u) continue;
            const float* gr = s_gray + yy*64;
            const float* wr = s_w + wb + dy*k;
            for (int dx = 0; dx < k; dx++) {
                int xx = x + dx - pad;
                if ((unsigned)xx >= 64u) continue;
                acc = fmaf(gr[xx], wr[dx], acc);
            }
        }
        dst[p] = acc;
    }
}

// ============================================================
// Kernel 2: top-k select + sort + nodes + 6-NN + edges.  grid = 64
// ============================================================
__global__ void __launch_bounds__(TC, 1)
graph_kernel(float* __restrict__ out)
{
    extern __shared__ unsigned char dsm[];
    float* s_resp = (float*)dsm;                              // 12288
    unsigned long long* s_sel = (unsigned long long*)(s_resp + NSCORE); // 256
    float* s_nx  = (float*)(s_sel + 256);                     // 196
    float* s_ny  = s_nx + MAXN;                               // 196
    int*   s_val = (int*)(s_ny + MAXN);                       // 196

    __shared__ unsigned s_hist[256];
    __shared__ int s_scan[385];
    __shared__ int s_wc[24*16];
    __shared__ unsigned s_pref;
    __shared__ int s_rem, s_nsel;

    const int b = blockIdx.x;
    const int t = threadIdx.x;
    const int lane = t & 31;
    const int warp = t >> 5;

    // ---- load responses into smem (vectorized) ----
    {
        const float4* src = (const float4*)(g_resp + (size_t)b*NSCORE);
        float4* dst = (float4*)s_resp;
        #pragma unroll
        for (int i = 0; i < NSCORE/4/TC; i++)
            dst[i*TC + t] = src[i*TC + t];
    }
    if (t == 0) { s_pref = 0; s_rem = MAXN; s_nsel = 0; }
    __syncthreads();

    // ---- radix select (4 passes, MSB-first) ----
    for (int pass = 0; pass < 4; pass++) {
        const int shift = 24 - 8*pass;
        const unsigned pref = s_pref;
        const int rem = s_rem;
        if (t < 256) s_hist[t] = 0;
        __syncthreads();
        #pragma unroll 4
        for (int it = 0; it < NSCORE/TC; it++) {
            int i = it*TC + t;
            unsigned u = enc_f(score_of(s_resp[i]));
            bool ok = (pass == 0) || ((u >> (shift + 8)) == (pref >> (shift + 8)));
            unsigned active = __ballot_sync(0xffffffffu, ok);
            if (ok) {
                unsigned bin = (u >> shift) & 0xFFu;
                unsigned mset = __match_any_sync(active, bin);
                if (lane == __ffs(mset) - 1)
                    atomicAdd(&s_hist[bin], __popc(mset));
            }
        }
        __syncthreads();
        // inclusive suffix scan S[d] = sum_{e>=d} hist[e]
        if (t < 256) s_scan[t] = (int)s_hist[t];
        __syncthreads();
        for (int off = 1; off < 256; off <<= 1) {
            int v = 0;
            if (t < 256 && t + off < 256) v = s_scan[t + off];
            __syncthreads();
            if (t < 256) s_scan[t] += v;
            __syncthreads();
        }
        // d = max{d : S[d] >= rem};  new rem = rem - S[d+1]
        if (t < 256) {
            int Sd  = s_scan[t];
            int Sd1 = (t == 255) ? 0 : s_scan[t + 1];
            if (Sd >= rem && Sd1 < rem) {
                s_pref = pref | ((unsigned)t << shift);
                s_rem  = rem - Sd1;
            }
        }
        __syncthreads();
    }
    const unsigned u_t = s_pref;
    const int ktie = s_rem;

    // ---- collect strictly-greater entries (unordered; sort fixes order) ----
    #pragma unroll 4
    for (int it = 0; it < NSCORE/TC; it++) {
        int i = it*TC + t;
        unsigned u = enc_f(score_of(s_resp[i]));
        if (u > u_t) {
            int pos = atomicAdd(&s_nsel, 1);
            s_sel[pos] = (((unsigned long long)u) << 32) | (unsigned)(~(unsigned)i);
        }
    }
    __syncthreads();
    const int cG = s_nsel;     // == 196 - ktie by radix invariant

    // ---- tie collection: rank-by-index via per-(chunk,warp) counts ----
    for (int chunk = 0; chunk < NSCORE/TC; chunk++) {
        int i = chunk*TC + t;
        bool pred = (enc_f(score_of(s_resp[i])) == u_t);
        unsigned bal = __ballot_sync(0xffffffffu, pred);
        if (lane == 0) s_wc[chunk*16 + warp] = __popc(bal);
    }
    __syncthreads();
    // inclusive prefix scan over 384 counts (element order == (chunk,warp,lane))
    if (t < 384) s_scan[t] = s_wc[t];
    __syncthreads();
    for (int off = 1; off < 384; off <<= 1) {
        int v = 0;
        if (t < 384 && t >= off) v = s_scan[t - off];
        __syncthreads();
        if (t < 384) s_scan[t] += v;
        __syncthreads();
    }
    for (int chunk = 0; chunk < NSCORE/TC; chunk++) {
        int i = chunk*TC + t;
        bool pred = (enc_f(score_of(s_resp[i])) == u_t);
        unsigned bal = __ballot_sync(0xffffffffu, pred);
        if (pred) {
            int cw = chunk*16 + warp;
            int rank = (cw > 0 ? s_scan[cw - 1] : 0)
                     + __popc(bal & ((1u << lane) - 1u));
            if (rank < ktie)
                s_sel[cG + rank] =
                    (((unsigned long long)u_t) << 32) | (unsigned)(~(unsigned)i);
        }
    }
    if (t >= MAXN && t < 256) s_sel[t] = 0ULL;
    __syncthreads();

    // ---- bitonic sort 256 keys descending (value desc, index asc) ----
    for (int kk = 2; kk <= 256; kk <<= 1) {
        for (int j = kk >> 1; j > 0; j >>= 1) {
            int ixj = t ^ j;
            if (t < 256 && ixj > t) {
                unsigned long long a = s_sel[t], c = s_sel[ixj];
                bool descend = ((t & kk) == 0);
                if (descend ? (a < c) : (a > c)) { s_sel[t] = c; s_sel[ixj] = a; }
            }
            __syncthreads();
        }
    }

    // ---- node features ----
    const float DIST_T = (float)(4.05 / 4.2);
    const float REC63x2 = __uint_as_float(0x3D020821u);  // f32(1/63)*2
    if (t < MAXN) {
        unsigned long long key = s_sel[t];
        unsigned idx = ~((unsigned)key);
        float rv = s_resp[idx];
        bool valid = (fabsf(rv) > 0.1f);
        int c  = idx >> 12;
        int rem2 = idx & 4095;
        int yi = rem2 >> 6, xi = rem2 & 63;
        float xc = __fsub_rn(__fmul_rn((float)xi, REC63x2), 1.0f);
        float yc = __fsub_rn(__fmul_rn((float)yi, REC63x2), 1.0f);
        float ecc = __fsqrt_rn(__fadd_rn(__fmul_rn(xc, xc), __fmul_rn(yc, yc)));
        float pol = (rv > 0.0f) ? 1.0f : ((rv < 0.0f) ? -1.0f : 0.0f);
        float vf = valid ? 1.0f : 0.0f;
        float* nrow = out + O_NODES + ((size_t)b*MAXN + t)*5;
        nrow[0] = xc * vf;
        nrow[1] = yc * vf;
        nrow[2] = pol * vf;
        nrow[3] = (float)c * vf;
        nrow[4] = ecc * vf;
        s_nx[t] = xc * vf;
        s_ny[t] = yc * vf;
        s_val[t] = valid ? 1 : 0;
        out[O_NV + b*MAXN + t] = vf;
        out[O_BI + b*MAXN + t] = (float)b;
    }
    __syncthreads();

    // ---- 6-NN + edges ----
    if (t < MAXN) {
        float xs = s_nx[t], ys = s_ny[t];
        int sv = s_val[t];
        unsigned long long nn[KNBR];
        #pragma unroll
        for (int q = 0; q < KNBR; q++) nn[q] = 0xFFFFFFFFFFFFFFFFULL;
        for (int j = 0; j < MAXN; j++) {
            float d;
            if (sv && s_val[j] && j != t) {
                float dx = __fsub_rn(xs, s_nx[j]);
                float dy = __fsub_rn(ys, s_ny[j]);
                float s2 = __fadd_rn(__fmul_rn(dx, dx), __fmul_rn(dy, dy));
                d = (s2 > 0.0f) ? __fsqrt_rn(s2) : 0.0f;
            } else {
                d = 1000000000.0f;
            }
            unsigned long long key =
                (((unsigned long long)__float_as_uint(d)) << 32) | (unsigned)j;
            if (key < nn[KNBR-1]) {
                nn[KNBR-1] = key;
                #pragma unroll
                for (int q = KNBR-1; q > 0; q--) {
                    if (nn[q] < nn[q-1]) {
                        unsigned long long tmp = nn[q]; nn[q] = nn[q-1]; nn[q-1] = tmp;
                    }
                }
            }
        }
        #pragma unroll
        for (int q = 0; q < KNBR; q++) {
            unsigned jd = (unsigned)nn[q];
            float d = __uint_as_float((unsigned)(nn[q] >> 32));
            bool ev = (d < DIST_T) && (sv != 0);
            float evf = ev ? 1.0f : 0.0f;
            float dx = __fsub_rn(s_nx[jd], xs);
            float dy = __fsub_rn(s_ny[jd], ys);
            float s2 = __fadd_rn(__fmul_rn(dx, dx), __fmul_rn(dy, dy));
            float cd = (s2 > 0.0f) ? __fsqrt_rn(s2) : 0.0f;
            size_t e = ((size_t)b*MAXN + t)*KNBR + q;
            out[O_EI + e]              = ev ? (float)(b*MAXN + t)  : 0.0f;
            out[O_EI + N_EDGE_TOT + e] = ev ? (float)(b*MAXN + jd) : 0.0f;
            out[O_EF + e*3 + 0] = dx * evf;
            out[O_EF + e*3 + 1] = dy * evf;
            out[O_EF + e*3 + 2] = cd * evf;
            out[O_EV + e] = evf;
        }
    }
}

extern "C" void kernel_launch(void* const* d_in, const int* in_sizes, int n_in,
                              void* d_out, int out_size)
{
    const float* img = (const float*)d_in[0];
    const float* w1  = (const float*)d_in[1];
    const float* w2  = (const float*)d_in[2];
    const float* w3  = (const float*)d_in[3];
    float* out = (float*)d_out;

    conv_kernel<<<dim3(B, 8), TB>>>(img, w1, w2, w3);

    const int smemC = NSCORE*4 + 256*8 + MAXN*4*3;  // 53552
    cudaFuncSetAttribute(graph_kernel,
                         cudaFuncAttributeMaxDynamicSharedMemorySize, smemC);
    graph_kernel<<<B, TC, smemC>>>(out);
}

// round 6
// speedup vs baseline: 2.1570x; 1.2417x over previous
#include <cuda_runtime.h>
#include <cstdint>

#define B          64
#define CROP       64
#define MAXN       196
#define KNBR       6
#define NSCORE     (3*CROP*CROP)        // 12288
#define WB         247
#define WS         18
#define TB         256                  // conv kernel threads
#define TC         1024                 // graph kernel threads
#define NIT        (NSCORE/TC)          // 12
#define NWARP      (TC/32)              // 32

typedef unsigned long long ull;

// output layout (f32, concatenated flattened tuple)
#define O_NODES 0
#define O_EI    62720
#define O_EF    213248
#define O_BI    439040
#define O_NV    451584
#define O_EV    464128
#define N_EDGE_TOT 75264                // B*196*6

__device__ float g_resp[B * NSCORE];    // 3 MB scratch

__device__ __forceinline__ float score_of(float r) {
    float m = fabsf(r);
    return (m > 0.1f) ? m : -1.0f;
}
__device__ __forceinline__ unsigned enc_f(float s) {
    unsigned b = __float_as_uint(s);
    return (b & 0x80000000u) ? ~b : (b | 0x80000000u);
}

// ============================================================
// Kernel 1: crop + gray + DoG convs.  grid = (64 batches, 8 slices)
// ============================================================
__global__ void __launch_bounds__(TB)
conv_kernel(const float* __restrict__ img,
            const float* __restrict__ w1,
            const float* __restrict__ w2,
            const float* __restrict__ w3)
{
    __shared__ float s_win[3*WS*WS];
    __shared__ float s_w[115];
    __shared__ float s_gray[CROP*CROP];

    const int b = blockIdx.x;
    const int slice = blockIdx.y;
    const int t = threadIdx.x;
    const float REC3 = __uint_as_float(0x3EAAAAABu);  // f32(1/3)

    int ch, obeg, oend;
    if (slice == 0)      { ch = 0; obeg = 0;              oend = 4096; }
    else if (slice <= 2) { ch = 1; obeg = (slice-1)*2048; oend = obeg + 2048; }
    else                 { ch = 2; obeg = (slice-3)*820;  oend = min(4096, obeg + 820); }
    int k, pad, wb;
    if (ch == 0)      { k = 3; pad = 1; wb = 0; }
    else if (ch == 1) { k = 5; pad = 2; wb = 9; }
    else              { k = 9; pad = 4; wb = 34; }
    const int rowLo = max(0, (obeg >> 6) - pad);
    const int rowHi = min(63, ((oend - 1) >> 6) + pad);

    if (t < 9)  s_w[t]      = w1[t];
    if (t < 25) s_w[9 + t]  = w2[t];
    if (t < 81) s_w[34 + t] = w3[t];
    for (int i = t; i < 3*WS*WS; i += TB) {
        int c = i / (WS*WS);
        int r = (i % (WS*WS)) / WS;
        int x = i % WS;
        s_win[i] = img[(((size_t)b*3 + c)*512 + (WB + r))*512 + (WB + x)];
    }
    __syncthreads();

    // crop (bilinear) + gray mean — only the rows this slice needs
    for (int p = rowLo*64 + t; p < (rowHi+1)*64; p += TB) {
        int iy = p >> 6, ix = p & 63;
        float bx = __fsub_rn(__fmul_rn((float)ix + 0.5f, 0.03125f), 1.0f);
        float by = __fsub_rn(__fmul_rn((float)iy + 0.5f, 0.03125f), 1.0f);
        float px = __fsub_rn(__fmul_rn(__fadd_rn(__fmul_rn(bx, 0.03125f), 1.0f), 256.0f), 0.5f);
        float py = __fsub_rn(__fmul_rn(__fadd_rn(__fmul_rn(by, 0.03125f), 1.0f), 256.0f), 0.5f);
        int ix0 = (int)floorf(px), iy0 = (int)floorf(py);
        float fx = __fsub_rn(px, (float)ix0);
        float fy = __fsub_rn(py, (float)iy0);
        float wx0 = __fsub_rn(1.0f, fx);
        float wy0 = __fsub_rn(1.0f, fy);
        int lx0 = ix0 - WB, ly0 = iy0 - WB;
        float sum = 0.0f;
        #pragma unroll
        for (int c = 0; c < 3; c++) {
            const float* wc = s_win + c*WS*WS;
            float v00 = wc[ly0*WS + lx0],     v01 = wc[ly0*WS + lx0 + 1];
            float v10 = wc[(ly0+1)*WS + lx0], v11 = wc[(ly0+1)*WS + lx0 + 1];
            float tx0 = __fadd_rn(__fmul_rn(v00, wx0), __fmul_rn(v01, fx));
            float tx1 = __fadd_rn(__fmul_rn(v10, wx0), __fmul_rn(v11, fx));
            float v   = __fadd_rn(__fmul_rn(tx0, wy0), __fmul_rn(tx1, fy));
            sum = __fadd_rn(sum, v);
        }
        s_gray[p] = __fmul_rn(sum, REC3);
    }
    __syncthreads();

    float* dst = g_resp + (size_t)b*NSCORE + ch*4096;
    for (int p = obeg + t; p < oend; p += TB) {
        int y = p >> 6, x = p & 63;
        float acc = 0.0f;
        for (int dy = 0; dy < k; dy++) {
            int yy = y + dy - pad;
            if ((unsigned)yy >= 64u) continue;
            const float* gr = s_gray + yy*64;
            const float* wr = s_w + wb + dy*k;
            for (int dx = 0; dx < k; dx++) {
                int xx = x + dx - pad;
                if ((unsigned)xx >= 64u) continue;
                acc = fmaf(gr[xx], wr[dx], acc);
            }
        }
        dst[p] = acc;
    }
}

// ============================================================
// Kernel 2: top-k select + sort + nodes + 6-NN + edges.  grid = 64
// ============================================================
__global__ void __launch_bounds__(TC, 1)
graph_kernel(float* __restrict__ out)
{
    extern __shared__ unsigned char dsm[];
    unsigned* s_whist = (unsigned*)dsm;                     // 32*256 u32 = 32768B
    ull* s_nn  = (ull*)dsm;                                 // alias: 196*2*6 u64 = 18816B
    ull* s_sel = (ull*)(dsm + 32768);                       // 256 u64
    float2* s_xy = (float2*)(dsm + 32768 + 2048);           // 196
    int* s_val  = (int*)(dsm + 32768 + 2048 + 1568);        // 196
    int* s_scan = s_val + 196;                              // 385
    int* s_wc   = s_scan + 385;                             // 384
    int* s_ws   = s_wc + 384;                               // 32
    __shared__ unsigned s_pref;
    __shared__ int s_rem;

    const int b = blockIdx.x;
    const int t = threadIdx.x;
    const int lane = t & 31, warp = t >> 5;

    // ---- load + encode: keys live in registers ----
    const float* resp = g_resp + (size_t)b*NSCORE;
    unsigned u[NIT];
    #pragma unroll
    for (int it = 0; it < NIT; it++)
        u[it] = enc_f(score_of(resp[it*TC + t]));
    if (t == 0) { s_pref = 0; s_rem = MAXN; }

    // ---- radix select, 4 passes, zero atomics ----
    for (int pass = 0; pass < 4; pass++) {
        const int shift = 24 - 8*pass;
        for (int i = t; i < NWARP*256; i += TC) s_whist[i] = 0;
        __syncthreads();
        const unsigned pref = s_pref;
        const int rem = s_rem;
        unsigned* wh = s_whist + warp*256;
        #pragma unroll
        for (int it = 0; it < NIT; it++) {
            unsigned uu = u[it];
            bool ok = (pass == 0) || ((uu >> (shift + 8)) == (pref >> (shift + 8)));
            unsigned active = __ballot_sync(0xffffffffu, ok);
            if (ok) {
                unsigned bin = (uu >> shift) & 255u;
                unsigned mset = __match_any_sync(active, bin);
                if (lane == __ffs(mset) - 1)
                    wh[bin] += __popc(mset);   // warp-private: no atomic needed
            }
        }
        __syncthreads();
        // reduce 32 warp-hists + inclusive SUFFIX scan over 256 bins
        int v = 0;
        if (t < 256) {
            #pragma unroll 8
            for (int w = 0; w < NWARP; w++) v += (int)s_whist[w*256 + t];
            #pragma unroll
            for (int off = 1; off < 32; off <<= 1) {
                int o = __shfl_down_sync(0xffffffffu, v, off);
                if (lane + off < 32) v += o;
            }
            if (lane == 0) s_ws[warp] = v;     // warp totals (warps 0..7)
        }
        __syncthreads();
        if (t < 8) {
            int wv = s_ws[t];
            #pragma unroll
            for (int off = 1; off < 8; off <<= 1) {
                int o = __shfl_down_sync(0xFFu, wv, off);
                if (t + off < 8) wv += o;
            }
            s_ws[t] = wv;                       // inclusive suffix of warp totals
        }
        __syncthreads();
        if (t < 256)
            s_scan[t] = v + ((warp < 7) ? s_ws[warp + 1] : 0);  // S[d]=sum_{e>=d}
        __syncthreads();
        if (t < 256) {
            int Sd  = s_scan[t];
            int Sd1 = (t == 255) ? 0 : s_scan[t + 1];
            if (Sd >= rem && Sd1 < rem) {
                s_pref = pref | ((unsigned)t << shift);
                s_rem  = rem - Sd1;
            }
        }
        __syncthreads();
    }
    const unsigned u_t = s_pref;
    const int ktie = s_rem;

    // ---- compaction: packed (greater<<16 | tie) ballot prefix-scan ----
    #pragma unroll
    for (int it = 0; it < NIT; it++) {
        unsigned bg = __ballot_sync(0xffffffffu, u[it] > u_t);
        unsigned bt = __ballot_sync(0xffffffffu, u[it] == u_t);
        if (lane == 0) s_wc[it*NWARP + warp] = (__popc(bg) << 16) | __popc(bt);
    }
    __syncthreads();
    if (t < 384) {
        int v = s_wc[t];
        #pragma unroll
        for (int off = 1; off < 32; off <<= 1) {
            int o = __shfl_up_sync(0xffffffffu, v, off);
            if (lane >= off) v += o;
        }
        s_scan[t] = v;                          // within-warp inclusive prefix
        if (lane == 31) s_ws[warp] = v;         // warp totals (warps 0..11)
    }
    __syncthreads();
    if (t < 12) {
        int wv = s_ws[t];
        #pragma unroll
        for (int off = 1; off < 16; off <<= 1) {
            int o = __shfl_up_sync(0xFFFu, wv, off);
            if (t >= off) wv += o;
        }
        s_ws[t] = wv;                           // inclusive prefix of warp totals
    }
    __syncthreads();
    const int cG = s_ws[11] >> 16;              // total strictly-greater = 196 - ktie
    #pragma unroll
    for (int it = 0; it < NIT; it++) {
        unsigned uu = u[it];
        bool g = (uu > u_t), e = (uu == u_t);
        unsigned bg = __ballot_sync(0xffffffffu, g);
        unsigned bt = __ballot_sync(0xffffffffu, e);
        int cw = it*NWARP + warp;
        int widx = cw >> 5;
        int incl = s_scan[cw] + ((widx > 0) ? s_ws[widx - 1] : 0);
        int excl = incl - ((__popc(bg) << 16) | __popc(bt));
        unsigned below = (1u << lane) - 1u;
        if (g) {
            int rank = (excl >> 16) + __popc(bg & below);
            s_sel[rank] = (((ull)uu) << 32) | (unsigned)(~(unsigned)(it*TC + t));
        }
        if (e) {
            int rank = (excl & 0xFFFF) + __popc(bt & below);
            if (rank < ktie)
                s_sel[cG + rank] = (((ull)u_t) << 32) | (unsigned)(~(unsigned)(it*TC + t));
        }
    }
    if (t >= MAXN && t < 256) s_sel[t] = 0ULL;
    __syncthreads();

    // ---- bitonic sort 256 keys descending: shuffle intra-warp, smem cross-warp ----
    ull k = (t < 256) ? s_sel[t] : 0ULL;
    if (t < 256) {
        #pragma unroll
        for (int kk = 2; kk <= 32; kk <<= 1) {
            #pragma unroll
            for (int j = kk >> 1; j > 0; j >>= 1) {
                ull o = __shfl_xor_sync(0xffffffffu, k, j);
                bool takeMax = (((t & kk) == 0) != ((t & j) != 0));
                k = takeMax ? (k > o ? k : o) : (k < o ? k : o);
            }
        }
    }
    #pragma unroll
    for (int kk = 64; kk <= 256; kk <<= 1) {
        for (int j = kk >> 1; j >= 32; j >>= 1) {
            __syncthreads();
            if (t < 256) s_sel[t] = k;
            __syncthreads();
            if (t < 256) {
                ull o = s_sel[t ^ j];
                bool takeMax = (((t & kk) == 0) != ((t & j) != 0));
                k = takeMax ? (k > o ? k : o) : (k < o ? k : o);
            }
        }
        if (t < 256) {
            #pragma unroll
            for (int j = 16; j > 0; j >>= 1) {
                ull o = __shfl_xor_sync(0xffffffffu, k, j);
                bool takeMax = (((t & kk) == 0) != ((t & j) != 0));
                k = takeMax ? (k > o ? k : o) : (k < o ? k : o);
            }
        }
    }

    // ---- node features ----
    const float DIST_T = (float)(4.05 / 4.2);
    const float REC63x2 = __uint_as_float(0x3D020821u);  // f32(1/63)*2
    if (t < MAXN) {
        unsigned idx = ~((unsigned)k);
        float rv = resp[idx];
        bool valid = (fabsf(rv) > 0.1f);
        int c  = idx >> 12;
        int rem2 = idx & 4095;
        int yi = rem2 >> 6, xi = rem2 & 63;
        float xc = __fsub_rn(__fmul_rn((float)xi, REC63x2), 1.0f);
        float yc = __fsub_rn(__fmul_rn((float)yi, REC63x2), 1.0f);
        float ecc = __fsqrt_rn(__fadd_rn(__fmul_rn(xc, xc), __fmul_rn(yc, yc)));
        float pol = (rv > 0.0f) ? 1.0f : ((rv < 0.0f) ? -1.0f : 0.0f);
        float vf = valid ? 1.0f : 0.0f;
        float* nrow = out + O_NODES + ((size_t)b*MAXN + t)*5;
        nrow[0] = xc * vf;
        nrow[1] = yc * vf;
        nrow[2] = pol * vf;
        nrow[3] = (float)c * vf;
        nrow[4] = ecc * vf;
        s_xy[t] = make_float2(xc * vf, yc * vf);
        s_val[t] = valid ? 1 : 0;
        out[O_NV + b*MAXN + t] = vf;
        out[O_BI + b*MAXN + t] = (float)b;
    }
    __syncthreads();

    // ---- 6-NN: 2 threads per node (j-halves), then merge ----
    {
        int node = -1, jBeg = 0, jEnd = 0, half = 0;
        if (t < MAXN)                          { node = t;       jBeg = 0;  jEnd = 98;   half = 0; }
        else if (t >= 512 && t < 512 + MAXN)   { node = t - 512; jBeg = 98; jEnd = MAXN; half = 1; }
        if (node >= 0) {
            float2 p = s_xy[node];
            int sv = s_val[node];
            ull nn[KNBR];
            #pragma unroll
            for (int q = 0; q < KNBR; q++) nn[q] = 0xFFFFFFFFFFFFFFFFULL;
            for (int j = jBeg; j < jEnd; j++) {
                float d;
                if (sv && s_val[j] && j != node) {
                    float2 pj = s_xy[j];
                    float dx = __fsub_rn(p.x, pj.x);
                    float dy = __fsub_rn(p.y, pj.y);
                    float s2 = __fadd_rn(__fmul_rn(dx, dx), __fmul_rn(dy, dy));
                    d = (s2 > 0.0f) ? __fsqrt_rn(s2) : 0.0f;
                } else {
                    d = 1000000000.0f;
                }
                ull key = (((ull)__float_as_uint(d)) << 32) | (unsigned)j;
                if (key < nn[KNBR-1]) {
                    nn[KNBR-1] = key;
                    #pragma unroll
                    for (int q = KNBR-1; q > 0; q--) {
                        if (nn[q] < nn[q-1]) { ull tmp = nn[q]; nn[q] = nn[q-1]; nn[q-1] = tmp; }
                    }
                }
            }
            ull* dst = s_nn + ((size_t)node*2 + half)*KNBR;
            #pragma unroll
            for (int q = 0; q < KNBR; q++) dst[q] = nn[q];
        }
    }
    __syncthreads();

    // ---- merge halves + emit edges ----
    if (t < MAXN) {
        const ull* A = s_nn + ((size_t)t*2)*KNBR;
        const ull* Bp = A + KNBR;
        float2 p = s_xy[t];
        int sv = s_val[t];
        int ia = 0, ib = 0;
        #pragma unroll
        for (int q = 0; q < KNBR; q++) {
            ull ka = A[ia], kb = Bp[ib];
            ull key;
            if (ka <= kb) { key = ka; ia++; } else { key = kb; ib++; }
            unsigned jd = (unsigned)key;
            float d = __uint_as_float((unsigned)(key >> 32));
            bool ev = (d < DIST_T) && (sv != 0);
            float evf = ev ? 1.0f : 0.0f;
            float2 pj = s_xy[jd];
            float dx = __fsub_rn(pj.x, p.x);
            float dy = __fsub_rn(pj.y, p.y);
            float s2 = __fadd_rn(__fmul_rn(dx, dx), __fmul_rn(dy, dy));
            float cd = (s2 > 0.0f) ? __fsqrt_rn(s2) : 0.0f;
            size_t e = ((size_t)b*MAXN + t)*KNBR + q;
            out[O_EI + e]              = ev ? (float)(b*MAXN + t)  : 0.0f;
            out[O_EI + N_EDGE_TOT + e] = ev ? (float)(b*MAXN + jd) : 0.0f;
            out[O_EF + e*3 + 0] = dx * evf;
            out[O_EF + e*3 + 1] = dy * evf;
            out[O_EF + e*3 + 2] = cd * evf;
            out[O_EV + e] = evf;
        }
    }
}

extern "C" void kernel_launch(void* const* d_in, const int* in_sizes, int n_in,
                              void* d_out, int out_size)
{
    const float* img = (const float*)d_in[0];
    const float* w1  = (const float*)d_in[1];
    const float* w2  = (const float*)d_in[2];
    const float* w3  = (const float*)d_in[3];
    float* out = (float*)d_out;

    conv_kernel<<<dim3(B, 8), TB>>>(img, w1, w2, w3);

    const int smemC = 41 * 1024;
    cudaFuncSetAttribute(graph_kernel,
                         cudaFuncAttributeMaxDynamicSharedMemorySize, smemC);
    graph_kernel<<<B, TC, smemC>>>(out);
}

// round 7
// speedup vs baseline: 2.8065x; 1.3011x over previous
#include <cuda_runtime.h>
#include <cstdint>

#define B          64
#define CROP       64
#define MAXN       196
#define KNBR       6
#define NSCORE     (3*CROP*CROP)        // 12288
#define WB         247
#define WS         18
#define TB         256                  // conv kernel threads
#define TC         1024                 // select kernel threads
#define TN         256                  // nn kernel threads
#define NIT        (NSCORE/TC)          // 12
#define NWARP      (TC/32)              // 32

typedef unsigned long long ull;

// output layout (f32, concatenated flattened tuple)
#define O_NODES 0
#define O_EI    62720
#define O_EF    213248
#define O_BI    439040
#define O_NV    451584
#define O_EV    464128
#define N_EDGE_TOT 75264                // B*196*6

__device__ float  g_resp[B * NSCORE];   // 3 MB scratch
__device__ float2 g_xy [B * MAXN];
__device__ int    g_val[B * MAXN];

__device__ __forceinline__ float score_of(float r) {
    float m = fabsf(r);
    return (m > 0.1f) ? m : -1.0f;
}
__device__ __forceinline__ unsigned enc_f(float s) {
    unsigned b = __float_as_uint(s);
    return (b & 0x80000000u) ? ~b : (b | 0x80000000u);
}

// ============================================================
// Kernel 1: crop + gray + DoG convs.  grid = (64 batches, 8 slices)
// ============================================================
__global__ void __launch_bounds__(TB)
conv_kernel(const float* __restrict__ img,
            const float* __restrict__ w1,
            const float* __restrict__ w2,
            const float* __restrict__ w3)
{
    __shared__ float s_win[3*WS*WS];
    __shared__ float s_w[115];
    __shared__ float s_gray[CROP*CROP];

    const int b = blockIdx.x;
    const int slice = blockIdx.y;
    const int t = threadIdx.x;
    const float REC3 = __uint_as_float(0x3EAAAAABu);  // f32(1/3)

    int ch, obeg, oend;
    if (slice == 0)      { ch = 0; obeg = 0;              oend = 4096; }
    else if (slice <= 2) { ch = 1; obeg = (slice-1)*2048; oend = obeg + 2048; }
    else                 { ch = 2; obeg = (slice-3)*820;  oend = min(4096, obeg + 820); }
    int k, pad, wb;
    if (ch == 0)      { k = 3; pad = 1; wb = 0; }
    else if (ch == 1) { k = 5; pad = 2; wb = 9; }
    else              { k = 9; pad = 4; wb = 34; }
    const int rowLo = max(0, (obeg >> 6) - pad);
    const int rowHi = min(63, ((oend - 1) >> 6) + pad);

    if (t < 9)  s_w[t]      = w1[t];
    if (t < 25) s_w[9 + t]  = w2[t];
    if (t < 81) s_w[34 + t] = w3[t];
    for (int i = t; i < 3*WS*WS; i += TB) {
        int c = i / (WS*WS);
        int r = (i % (WS*WS)) / WS;
        int x = i % WS;
        s_win[i] = img[(((size_t)b*3 + c)*512 + (WB + r))*512 + (WB + x)];
    }
    __syncthreads();

    for (int p = rowLo*64 + t; p < (rowHi+1)*64; p += TB) {
        int iy = p >> 6, ix = p & 63;
        float bx = __fsub_rn(__fmul_rn((float)ix + 0.5f, 0.03125f), 1.0f);
        float by = __fsub_rn(__fmul_rn((float)iy + 0.5f, 0.03125f), 1.0f);
        float px = __fsub_rn(__fmul_rn(__fadd_rn(__fmul_rn(bx, 0.03125f), 1.0f), 256.0f), 0.5f);
        float py = __fsub_rn(__fmul_rn(__fadd_rn(__fmul_rn(by, 0.03125f), 1.0f), 256.0f), 0.5f);
        int ix0 = (int)floorf(px), iy0 = (int)floorf(py);
        float fx = __fsub_rn(px, (float)ix0);
        float fy = __fsub_rn(py, (float)iy0);
        float wx0 = __fsub_rn(1.0f, fx);
        float wy0 = __fsub_rn(1.0f, fy);
        int lx0 = ix0 - WB, ly0 = iy0 - WB;
        float sum = 0.0f;
        #pragma unroll
        for (int c = 0; c < 3; c++) {
            const float* wc = s_win + c*WS*WS;
            float v00 = wc[ly0*WS + lx0],     v01 = wc[ly0*WS + lx0 + 1];
            float v10 = wc[(ly0+1)*WS + lx0], v11 = wc[(ly0+1)*WS + lx0 + 1];
            float tx0 = __fadd_rn(__fmul_rn(v00, wx0), __fmul_rn(v01, fx));
            float tx1 = __fadd_rn(__fmul_rn(v10, wx0), __fmul_rn(v11, fx));
            float v   = __fadd_rn(__fmul_rn(tx0, wy0), __fmul_rn(tx1, fy));
            sum = __fadd_rn(sum, v);
        }
        s_gray[p] = __fmul_rn(sum, REC3);
    }
    __syncthreads();

    float* dst = g_resp + (size_t)b*NSCORE + ch*4096;
    for (int p = obeg + t; p < oend; p += TB) {
        int y = p >> 6, x = p & 63;
        float acc = 0.0f;
        for (int dy = 0; dy < k; dy++) {
            int yy = y + dy - pad;
            if ((unsigned)yy >= 64u) continue;
            const float* gr = s_gray + yy*64;
            const float* wr = s_w + wb + dy*k;
            for (int dx = 0; dx < k; dx++) {
                int xx = x + dx - pad;
                if ((unsigned)xx >= 64u) continue;
                acc = fmaf(gr[xx], wr[dx], acc);
            }
        }
        dst[p] = acc;
    }
}

// ============================================================
// Kernel 2: top-k select + sort + node outputs.  grid = 64
// ============================================================
__global__ void __launch_bounds__(TC, 1)
select_kernel(float* __restrict__ out)
{
    extern __shared__ unsigned char dsm[];
    unsigned* s_whist = (unsigned*)dsm;                     // 32*256 u32 = 32768B
    ull* s_sel = (ull*)(dsm + 32768);                       // 256 u64
    int* s_scan = (int*)(dsm + 32768 + 2048);               // 385
    int* s_wc   = s_scan + 385;                             // 384
    int* s_ws   = s_wc + 384;                               // 32
    __shared__ unsigned s_pref;
    __shared__ int s_rem;

    const int b = blockIdx.x;
    const int t = threadIdx.x;
    const int lane = t & 31, warp = t >> 5;

    // ---- load + encode: keys live in registers ----
    const float* resp = g_resp + (size_t)b*NSCORE;
    unsigned u[NIT];
    #pragma unroll
    for (int it = 0; it < NIT; it++)
        u[it] = enc_f(score_of(resp[it*TC + t]));
    if (t == 0) { s_pref = 0; s_rem = MAXN; }

    // ---- radix select, 4 passes, zero atomics ----
    for (int pass = 0; pass < 4; pass++) {
        const int shift = 24 - 8*pass;
        for (int i = t; i < NWARP*256; i += TC) s_whist[i] = 0;
        __syncthreads();
        const unsigned pref = s_pref;
        const int rem = s_rem;
        unsigned* wh = s_whist + warp*256;
        #pragma unroll
        for (int it = 0; it < NIT; it++) {
            unsigned uu = u[it];
            bool ok = (pass == 0) || ((uu >> (shift + 8)) == (pref >> (shift + 8)));
            unsigned active = __ballot_sync(0xffffffffu, ok);
            if (ok) {
                unsigned bin = (uu >> shift) & 255u;
                unsigned mset = __match_any_sync(active, bin);
                if (lane == __ffs(mset) - 1)
                    wh[bin] += __popc(mset);
            }
        }
        __syncthreads();
        int v = 0;
        if (t < 256) {
            #pragma unroll 8
            for (int w = 0; w < NWARP; w++) v += (int)s_whist[w*256 + t];
            #pragma unroll
            for (int off = 1; off < 32; off <<= 1) {
                int o = __shfl_down_sync(0xffffffffu, v, off);
                if (lane + off < 32) v += o;
            }
            if (lane == 0) s_ws[warp] = v;
        }
        __syncthreads();
        if (t < 8) {
            int wv = s_ws[t];
            #pragma unroll
            for (int off = 1; off < 8; off <<= 1) {
                int o = __shfl_down_sync(0xFFu, wv, off);
                if (t + off < 8) wv += o;
            }
            s_ws[t] = wv;
        }
        __syncthreads();
        if (t < 256)
            s_scan[t] = v + ((warp < 7) ? s_ws[warp + 1] : 0);
        __syncthreads();
        if (t < 256) {
            int Sd  = s_scan[t];
            int Sd1 = (t == 255) ? 0 : s_scan[t + 1];
            if (Sd >= rem && Sd1 < rem) {
                s_pref = pref | ((unsigned)t << shift);
                s_rem  = rem - Sd1;
            }
        }
        __syncthreads();
    }
    const unsigned u_t = s_pref;
    const int ktie = s_rem;

    // ---- compaction: packed (greater<<16 | tie) ballot prefix-scan ----
    #pragma unroll
    for (int it = 0; it < NIT; it++) {
        unsigned bg = __ballot_sync(0xffffffffu, u[it] > u_t);
        unsigned bt = __ballot_sync(0xffffffffu, u[it] == u_t);
        if (lane == 0) s_wc[it*NWARP + warp] = (__popc(bg) << 16) | __popc(bt);
    }
    __syncthreads();
    if (t < 384) {
        int v = s_wc[t];
        #pragma unroll
        for (int off = 1; off < 32; off <<= 1) {
            int o = __shfl_up_sync(0xffffffffu, v, off);
            if (lane >= off) v += o;
        }
        s_scan[t] = v;
        if (lane == 31) s_ws[warp] = v;
    }
    __syncthreads();
    if (t < 12) {
        int wv = s_ws[t];
        #pragma unroll
        for (int off = 1; off < 16; off <<= 1) {
            int o = __shfl_up_sync(0xFFFu, wv, off);
            if (t >= off) wv += o;
        }
        s_ws[t] = wv;
    }
    __syncthreads();
    const int cG = s_ws[11] >> 16;
    #pragma unroll
    for (int it = 0; it < NIT; it++) {
        unsigned uu = u[it];
        bool g = (uu > u_t), e = (uu == u_t);
        unsigned bg = __ballot_sync(0xffffffffu, g);
        unsigned bt = __ballot_sync(0xffffffffu, e);
        int cw = it*NWARP + warp;
        int widx = cw >> 5;
        int incl = s_scan[cw] + ((widx > 0) ? s_ws[widx - 1] : 0);
        int excl = incl - ((__popc(bg) << 16) | __popc(bt));
        unsigned below = (1u << lane) - 1u;
        if (g) {
            int rank = (excl >> 16) + __popc(bg & below);
            s_sel[rank] = (((ull)uu) << 32) | (unsigned)(~(unsigned)(it*TC + t));
        }
        if (e) {
            int rank = (excl & 0xFFFF) + __popc(bt & below);
            if (rank < ktie)
                s_sel[cG + rank] = (((ull)u_t) << 32) | (unsigned)(~(unsigned)(it*TC + t));
        }
    }
    if (t >= MAXN && t < 256) s_sel[t] = 0ULL;
    __syncthreads();

    // ---- bitonic sort 256 keys descending ----
    ull k = (t < 256) ? s_sel[t] : 0ULL;
    if (t < 256) {
        #pragma unroll
        for (int kk = 2; kk <= 32; kk <<= 1) {
            #pragma unroll
            for (int j = kk >> 1; j > 0; j >>= 1) {
                ull o = __shfl_xor_sync(0xffffffffu, k, j);
                bool takeMax = (((t & kk) == 0) != ((t & j) != 0));
                k = takeMax ? (k > o ? k : o) : (k < o ? k : o);
            }
        }
    }
    #pragma unroll
    for (int kk = 64; kk <= 256; kk <<= 1) {
        for (int j = kk >> 1; j >= 32; j >>= 1) {
            __syncthreads();
            if (t < 256) s_sel[t] = k;
            __syncthreads();
            if (t < 256) {
                ull o = s_sel[t ^ j];
                bool takeMax = (((t & kk) == 0) != ((t & j) != 0));
                k = takeMax ? (k > o ? k : o) : (k < o ? k : o);
            }
        }
        if (t < 256) {
            #pragma unroll
            for (int j = 16; j > 0; j >>= 1) {
                ull o = __shfl_xor_sync(0xffffffffu, k, j);
                bool takeMax = (((t & kk) == 0) != ((t & j) != 0));
                k = takeMax ? (k > o ? k : o) : (k < o ? k : o);
            }
        }
    }

    // ---- node features + export (x, y, valid) for the NN kernel ----
    const float REC63x2 = __uint_as_float(0x3D020821u);  // f32(1/63)*2
    if (t < MAXN) {
        unsigned idx = ~((unsigned)k);
        float rv = resp[idx];
        bool valid = (fabsf(rv) > 0.1f);
        int c  = idx >> 12;
        int rem2 = idx & 4095;
        int yi = rem2 >> 6, xi = rem2 & 63;
        float xc = __fsub_rn(__fmul_rn((float)xi, REC63x2), 1.0f);
        float yc = __fsub_rn(__fmul_rn((float)yi, REC63x2), 1.0f);
        float ecc = __fsqrt_rn(__fadd_rn(__fmul_rn(xc, xc), __fmul_rn(yc, yc)));
        float pol = (rv > 0.0f) ? 1.0f : ((rv < 0.0f) ? -1.0f : 0.0f);
        float vf = valid ? 1.0f : 0.0f;
        float* nrow = out + O_NODES + ((size_t)b*MAXN + t)*5;
        nrow[0] = xc * vf;
        nrow[1] = yc * vf;
        nrow[2] = pol * vf;
        nrow[3] = (float)c * vf;
        nrow[4] = ecc * vf;
        g_xy [b*MAXN + t] = make_float2(xc * vf, yc * vf);
        g_val[b*MAXN + t] = valid ? 1 : 0;
        out[O_NV + b*MAXN + t] = vf;
        out[O_BI + b*MAXN + t] = (float)b;
    }
}

// ============================================================
// Kernel 3: 6-NN + edges, one warp per node.  grid = (64, 25)
// ============================================================
__global__ void __launch_bounds__(TN)
nn_kernel(float* __restrict__ out)
{
    __shared__ float2 s_xy[MAXN];
    __shared__ int s_val[MAXN];

    const int b = blockIdx.x;
    const int t = threadIdx.x;
    const int lane = t & 31, warp = t >> 5;

    if (t < MAXN) {
        s_xy[t]  = g_xy [b*MAXN + t];
        s_val[t] = g_val[b*MAXN + t];
    }
    __syncthreads();

    const int node = blockIdx.y * (TN/32) + warp;
    if (node >= MAXN) return;

    const float2 p = s_xy[node];
    const int sv = s_val[node];

    // per-lane top-6 over candidates j = lane + 32*m
    ull nn[KNBR];
    #pragma unroll
    for (int q = 0; q < KNBR; q++) nn[q] = 0xFFFFFFFFFFFFFFFFULL;
    #pragma unroll
    for (int m = 0; m < 7; m++) {
        int j = lane + m*32;
        if (j < MAXN) {
            float d;
            if (sv && s_val[j] && j != node) {
                float2 pj = s_xy[j];
                float dx = __fsub_rn(p.x, pj.x);
                float dy = __fsub_rn(p.y, pj.y);
                float s2 = __fadd_rn(__fmul_rn(dx, dx), __fmul_rn(dy, dy));
                d = (s2 > 0.0f) ? __fsqrt_rn(s2) : 0.0f;
            } else {
                d = 1000000000.0f;
            }
            ull key = (((ull)__float_as_uint(d)) << 32) | (unsigned)j;
            #pragma unroll
            for (int q = 0; q < KNBR; q++) {
                if (key < nn[q]) { ull tmp = nn[q]; nn[q] = key; key = tmp; }
            }
        }
    }

    // 6-round tournament merge: keys are unique, owner pops its head
    ull res = 0xFFFFFFFFFFFFFFFFULL;
    #pragma unroll
    for (int q = 0; q < KNBR; q++) {
        ull h = nn[0];
        #pragma unroll
        for (int off = 16; off > 0; off >>= 1) {
            ull o = __shfl_xor_sync(0xffffffffu, h, off);
            h = (o < h) ? o : h;
        }
        if (lane == q) res = h;
        if (nn[0] == h) {
            #pragma unroll
            for (int r = 0; r < KNBR-1; r++) nn[r] = nn[r+1];
            nn[KNBR-1] = 0xFFFFFFFFFFFFFFFFULL;
        }
    }

    // lanes 0..5 emit edges
    if (lane < KNBR) {
        const float DIST_T = (float)(4.05 / 4.2);
        unsigned jd = (unsigned)res;
        float d = __uint_as_float((unsigned)(res >> 32));
        bool ev = (d < DIST_T) && (sv != 0);
        float evf = ev ? 1.0f : 0.0f;
        float2 pj = s_xy[jd];
        float dx = __fsub_rn(pj.x, p.x);
        float dy = __fsub_rn(pj.y, p.y);
        float s2 = __fadd_rn(__fmul_rn(dx, dx), __fmul_rn(dy, dy));
        float cd = (s2 > 0.0f) ? __fsqrt_rn(s2) : 0.0f;
        size_t e = ((size_t)b*MAXN + node)*KNBR + lane;
        out[O_EI + e]              = ev ? (float)(b*MAXN + node) : 0.0f;
        out[O_EI + N_EDGE_TOT + e] = ev ? (float)(b*MAXN + jd)   : 0.0f;
        out[O_EF + e*3 + 0] = dx * evf;
        out[O_EF + e*3 + 1] = dy * evf;
        out[O_EF + e*3 + 2] = cd * evf;
        out[O_EV + e] = evf;
    }
}

extern "C" void kernel_launch(void* const* d_in, const int* in_sizes, int n_in,
                              void* d_out, int out_size)
{
    const float* img = (const float*)d_in[0];
    const float* w1  = (const float*)d_in[1];
    const float* w2  = (const float*)d_in[2];
    const float* w3  = (const float*)d_in[3];
    float* out = (float*)d_out;

    conv_kernel<<<dim3(B, 8), TB>>>(img, w1, w2, w3);

    const int smemC = 40 * 1024;
    cudaFuncSetAttribute(select_kernel,
                         cudaFuncAttributeMaxDynamicSharedMemorySize, smemC);
    select_kernel<<<B, TC, smemC>>>(out);

    nn_kernel<<<dim3(B, (MAXN + TN/32 - 1) / (TN/32)), TN>>>(out);
}

// round 8
// speedup vs baseline: 3.7826x; 1.3478x over previous
#include <cuda_runtime.h>
#include <cstdint>

#define B          64
#define CROP       64
#define MAXN       196
#define KNBR       6
#define NSCORE     (3*CROP*CROP)        // 12288
#define WB         247
#define WS         18
#define TC         1024                 // main kernel threads
#define TN         256                  // nn kernel threads
#define NIT        (NSCORE/TC)          // 12
#define NWARP      (TC/32)              // 32
#define GPITCH     72                   // padded gray pitch (64 + 2*4)

typedef unsigned long long ull;

// output layout (f32, concatenated flattened tuple)
#define O_NODES 0
#define O_EI    62720
#define O_EF    213248
#define O_BI    439040
#define O_NV    451584
#define O_EV    464128
#define N_EDGE_TOT 75264                // B*196*6

__device__ float2 g_xy [B * MAXN];
__device__ int    g_val[B * MAXN];

__device__ __forceinline__ float score_of(float r) {
    float m = fabsf(r);
    return (m > 0.1f) ? m : -1.0f;
}
__device__ __forceinline__ unsigned enc_f(float s) {
    unsigned b = __float_as_uint(s);
    return (b & 0x80000000u) ? ~b : (b | 0x80000000u);
}

// 4 consecutive outputs (one row) of a KxK SAME conv on the zero-padded gray.
// Tap order (dy asc, dx asc) identical to the scalar version; padded taps are
// fmaf(0, w, acc) == acc exactly, so results are bit-identical.
template<int K, int PAD, int WOFF>
__device__ __forceinline__ float4 conv_quad(const float* __restrict__ s_gpad,
                                            const float* __restrict__ s_w,
                                            int y, int x0)
{
    float a0 = 0.f, a1 = 0.f, a2 = 0.f, a3 = 0.f;
    #pragma unroll
    for (int dy = 0; dy < K; dy++) {
        const float* gr = s_gpad + (y + dy - PAD + 4)*GPITCH + (x0 - PAD + 4);
        float gv[K + 3];
        #pragma unroll
        for (int i = 0; i < K + 3; i++) gv[i] = gr[i];
        const float* wr = s_w + WOFF + dy*K;
        #pragma unroll
        for (int dx = 0; dx < K; dx++) {
            float w = wr[dx];
            a0 = fmaf(gv[dx],     w, a0);
            a1 = fmaf(gv[dx + 1], w, a1);
            a2 = fmaf(gv[dx + 2], w, a2);
            a3 = fmaf(gv[dx + 3], w, a3);
        }
    }
    return make_float4(a0, a1, a2, a3);
}

// ============================================================
// Kernel 1 (fused): crop+gray+conv -> top-k select -> nodes.  grid = 64
// ============================================================
__global__ void __launch_bounds__(TC, 1)
main_kernel(const float* __restrict__ img,
            const float* __restrict__ w1,
            const float* __restrict__ w2,
            const float* __restrict__ w3,
            float* __restrict__ out)
{
    extern __shared__ unsigned char dsm[];
    ull*      s_sel   = (ull*)dsm;                        // 256          (2048 B)
    float*    s_resp  = (float*)(dsm + 2048);             // 12288        (49152 B)
    float*    s_gpad  = s_resp + NSCORE;                  // 72*72 = 5184 (20736 B)
    float*    s_win   = s_gpad + GPITCH*GPITCH;           // 972
    float*    s_w     = s_win + 3*WS*WS;                  // 115
    unsigned* s_whist = (unsigned*)(s_w + 115);           // 32*256       (32768 B)
    int*      s_scan  = (int*)(s_whist + NWARP*256);      // 385
    int*      s_wc    = s_scan + 385;                     // 384
    int*      s_ws    = s_wc + 384;                       // 32
    __shared__ unsigned s_pref;
    __shared__ int s_rem;

    const int b = blockIdx.x;
    const int t = threadIdx.x;
    const int lane = t & 31, warp = t >> 5;
    const float REC3 = __uint_as_float(0x3EAAAAABu);      // f32(1/3)

    // ---- load weights + window, zero padded gray ----
    if (t < 9)  s_w[t]      = w1[t];
    if (t < 25) s_w[9 + t]  = w2[t];
    if (t < 81) s_w[34 + t] = w3[t];
    if (t < 3*WS*WS) {
        int c = t / (WS*WS);
        int r = (t % (WS*WS)) / WS;
        int x = t % WS;
        s_win[t] = img[(((size_t)b*3 + c)*512 + (WB + r))*512 + (WB + x)];
    }
    for (int i = t; i < GPITCH*GPITCH; i += TC) s_gpad[i] = 0.0f;
    __syncthreads();

    // ---- crop (bilinear) + gray mean: 4 px per thread ----
    #pragma unroll
    for (int g = 0; g < 4; g++) {
        int p = g*TC + t;
        int iy = p >> 6, ix = p & 63;
        float bx = __fsub_rn(__fmul_rn((float)ix + 0.5f, 0.03125f), 1.0f);
        float by = __fsub_rn(__fmul_rn((float)iy + 0.5f, 0.03125f), 1.0f);
        float px = __fsub_rn(__fmul_rn(__fadd_rn(__fmul_rn(bx, 0.03125f), 1.0f), 256.0f), 0.5f);
        float py = __fsub_rn(__fmul_rn(__fadd_rn(__fmul_rn(by, 0.03125f), 1.0f), 256.0f), 0.5f);
        int ix0 = (int)floorf(px), iy0 = (int)floorf(py);
        float fx = __fsub_rn(px, (float)ix0);
        float fy = __fsub_rn(py, (float)iy0);
        float wx0 = __fsub_rn(1.0f, fx);
        float wy0 = __fsub_rn(1.0f, fy);
        int lx0 = ix0 - WB, ly0 = iy0 - WB;
        float sum = 0.0f;
        #pragma unroll
        for (int c = 0; c < 3; c++) {
            const float* wc = s_win + c*WS*WS;
            float v00 = wc[ly0*WS + lx0],     v01 = wc[ly0*WS + lx0 + 1];
            float v10 = wc[(ly0+1)*WS + lx0], v11 = wc[(ly0+1)*WS + lx0 + 1];
            float tx0 = __fadd_rn(__fmul_rn(v00, wx0), __fmul_rn(v01, fx));
            float tx1 = __fadd_rn(__fmul_rn(v10, wx0), __fmul_rn(v11, fx));
            float v   = __fadd_rn(__fmul_rn(tx0, wy0), __fmul_rn(tx1, fy));
            sum = __fadd_rn(sum, v);
        }
        s_gpad[(iy + 4)*GPITCH + ix + 4] = __fmul_rn(sum, REC3);
    }
    __syncthreads();

    // ---- 3 DoG convs: each thread does one 4-wide quad per channel ----
    {
        int y  = t >> 4;            // row (p = 4t)
        int x0 = (t & 15) * 4;      // col base
        float4* rq = (float4*)s_resp;
        rq[t]          = conv_quad<3, 1, 0 >(s_gpad, s_w, y, x0);
        rq[1024 + t]   = conv_quad<5, 2, 9 >(s_gpad, s_w, y, x0);
        rq[2048 + t]   = conv_quad<9, 4, 34>(s_gpad, s_w, y, x0);
    }
    if (t == 0) { s_pref = 0; s_rem = MAXN; }
    __syncthreads();

    // ---- encode keys (linear it*TC + t layout) ----
    unsigned u[NIT];
    #pragma unroll
    for (int it = 0; it < NIT; it++)
        u[it] = enc_f(score_of(s_resp[it*TC + t]));

    // ---- radix select, 4 passes, zero atomics ----
    for (int pass = 0; pass < 4; pass++) {
        const int shift = 24 - 8*pass;
        for (int i = t; i < NWARP*256; i += TC) s_whist[i] = 0;
        __syncthreads();
        const unsigned pref = s_pref;
        const int rem = s_rem;
        unsigned* wh = s_whist + warp*256;
        #pragma unroll
        for (int it = 0; it < NIT; it++) {
            unsigned uu = u[it];
            bool ok = (pass == 0) || ((uu >> (shift + 8)) == (pref >> (shift + 8)));
            unsigned active = __ballot_sync(0xffffffffu, ok);
            if (ok) {
                unsigned bin = (uu >> shift) & 255u;
                unsigned mset = __match_any_sync(active, bin);
                if (lane == __ffs(mset) - 1)
                    wh[bin] += __popc(mset);
            }
        }
        __syncthreads();
        int v = 0;
        if (t < 256) {
            #pragma unroll 8
            for (int w = 0; w < NWARP; w++) v += (int)s_whist[w*256 + t];
            #pragma unroll
            for (int off = 1; off < 32; off <<= 1) {
                int o = __shfl_down_sync(0xffffffffu, v, off);
                if (lane + off < 32) v += o;
            }
            if (lane == 0) s_ws[warp] = v;
        }
        __syncthreads();
        if (t < 8) {
            int wv = s_ws[t];
            #pragma unroll
            for (int off = 1; off < 8; off <<= 1) {
                int o = __shfl_down_sync(0xFFu, wv, off);
                if (t + off < 8) wv += o;
            }
            s_ws[t] = wv;
        }
        __syncthreads();
        if (t < 256)
            s_scan[t] = v + ((warp < 7) ? s_ws[warp + 1] : 0);   // suffix sums
        __syncthreads();
        if (t < 256) {
            int Sd  = s_scan[t];
            int Sd1 = (t == 255) ? 0 : s_scan[t + 1];
            if (Sd >= rem && Sd1 < rem) {
                s_pref = pref | ((unsigned)t << shift);
                s_rem  = rem - Sd1;
            }
        }
        __syncthreads();
    }
    const unsigned u_t = s_pref;
    const int ktie = s_rem;

    // ---- compaction: packed (greater<<16 | tie) ballot prefix-scan ----
    #pragma unroll
    for (int it = 0; it < NIT; it++) {
        unsigned bg = __ballot_sync(0xffffffffu, u[it] > u_t);
        unsigned bt = __ballot_sync(0xffffffffu, u[it] == u_t);
        if (lane == 0) s_wc[it*NWARP + warp] = (__popc(bg) << 16) | __popc(bt);
    }
    __syncthreads();
    if (t < 384) {
        int v = s_wc[t];
        #pragma unroll
        for (int off = 1; off < 32; off <<= 1) {
            int o = __shfl_up_sync(0xffffffffu, v, off);
            if (lane >= off) v += o;
        }
        s_scan[t] = v;
        if (lane == 31) s_ws[warp] = v;
    }
    __syncthreads();
    if (t < 12) {
        int wv = s_ws[t];
        #pragma unroll
        for (int off = 1; off < 16; off <<= 1) {
            int o = __shfl_up_sync(0xFFFu, wv, off);
            if (t >= off) wv += o;
        }
        s_ws[t] = wv;
    }
    __syncthreads();
    const int cG = s_ws[11] >> 16;
    #pragma unroll
    for (int it = 0; it < NIT; it++) {
        unsigned uu = u[it];
        bool g = (uu > u_t), e = (uu == u_t);
        unsigned bg = __ballot_sync(0xffffffffu, g);
        unsigned bt = __ballot_sync(0xffffffffu, e);
        int cw = it*NWARP + warp;
        int widx = cw >> 5;
        int incl = s_scan[cw] + ((widx > 0) ? s_ws[widx - 1] : 0);
        int excl = incl - ((__popc(bg) << 16) | __popc(bt));
        unsigned below = (1u << lane) - 1u;
        if (g) {
            int rank = (excl >> 16) + __popc(bg & below);
            s_sel[rank] = (((ull)uu) << 32) | (unsigned)(~(unsigned)(it*TC + t));
        }
        if (e) {
            int rank = (excl & 0xFFFF) + __popc(bt & below);
            if (rank < ktie)
                s_sel[cG + rank] = (((ull)u_t) << 32) | (unsigned)(~(unsigned)(it*TC + t));
        }
    }
    if (t >= MAXN && t < 256) s_sel[t] = 0ULL;
    __syncthreads();

    // ---- bitonic sort 256 keys descending ----
    ull k = (t < 256) ? s_sel[t] : 0ULL;
    if (t < 256) {
        #pragma unroll
        for (int kk = 2; kk <= 32; kk <<= 1) {
            #pragma unroll
            for (int j = kk >> 1; j > 0; j >>= 1) {
                ull o = __shfl_xor_sync(0xffffffffu, k, j);
                bool takeMax = (((t & kk) == 0) != ((t & j) != 0));
                k = takeMax ? (k > o ? k : o) : (k < o ? k : o);
            }
        }
    }
    #pragma unroll
    for (int kk = 64; kk <= 256; kk <<= 1) {
        for (int j = kk >> 1; j >= 32; j >>= 1) {
            __syncthreads();
            if (t < 256) s_sel[t] = k;
            __syncthreads();
            if (t < 256) {
                ull o = s_sel[t ^ j];
                bool takeMax = (((t & kk) == 0) != ((t & j) != 0));
                k = takeMax ? (k > o ? k : o) : (k < o ? k : o);
            }
        }
        if (t < 256) {
            #pragma unroll
            for (int j = 16; j > 0; j >>= 1) {
                ull o = __shfl_xor_sync(0xffffffffu, k, j);
                bool takeMax = (((t & kk) == 0) != ((t & j) != 0));
                k = takeMax ? (k > o ? k : o) : (k < o ? k : o);
            }
        }
    }

    // ---- node features + export (x, y, valid) for the NN kernel ----
    const float REC63x2 = __uint_as_float(0x3D020821u);  // f32(1/63)*2
    if (t < MAXN) {
        unsigned idx = ~((unsigned)k);
        float rv = s_resp[idx];
        bool valid = (fabsf(rv) > 0.1f);
        int c  = idx >> 12;
        int rem2 = idx & 4095;
        int yi = rem2 >> 6, xi = rem2 & 63;
        float xc = __fsub_rn(__fmul_rn((float)xi, REC63x2), 1.0f);
        float yc = __fsub_rn(__fmul_rn((float)yi, REC63x2), 1.0f);
        float ecc = __fsqrt_rn(__fadd_rn(__fmul_rn(xc, xc), __fmul_rn(yc, yc)));
        float pol = (rv > 0.0f) ? 1.0f : ((rv < 0.0f) ? -1.0f : 0.0f);
        float vf = valid ? 1.0f : 0.0f;
        float* nrow = out + O_NODES + ((size_t)b*MAXN + t)*5;
        nrow[0] = xc * vf;
        nrow[1] = yc * vf;
        nrow[2] = pol * vf;
        nrow[3] = (float)c * vf;
        nrow[4] = ecc * vf;
        g_xy [b*MAXN + t] = make_float2(xc * vf, yc * vf);
        g_val[b*MAXN + t] = valid ? 1 : 0;
        out[O_NV + b*MAXN + t] = vf;
        out[O_BI + b*MAXN + t] = (float)b;
    }
}

// ============================================================
// Kernel 2: 6-NN + edges, one warp per node.  grid = (64, 25)
// ============================================================
__global__ void __launch_bounds__(TN)
nn_kernel(float* __restrict__ out)
{
    __shared__ float2 s_xy[MAXN];
    __shared__ int s_val[MAXN];

    const int b = blockIdx.x;
    const int t = threadIdx.x;
    const int lane = t & 31, warp = t >> 5;

    if (t < MAXN) {
        s_xy[t]  = g_xy [b*MAXN + t];
        s_val[t] = g_val[b*MAXN + t];
    }
    __syncthreads();

    const int node = blockIdx.y * (TN/32) + warp;
    if (node >= MAXN) return;

    const float2 p = s_xy[node];
    const int sv = s_val[node];

    ull nn[KNBR];
    #pragma unroll
    for (int q = 0; q < KNBR; q++) nn[q] = 0xFFFFFFFFFFFFFFFFULL;
    #pragma unroll
    for (int m = 0; m < 7; m++) {
        int j = lane + m*32;
        if (j < MAXN) {
            float d;
            if (sv && s_val[j] && j != node) {
                float2 pj = s_xy[j];
                float dx = __fsub_rn(p.x, pj.x);
                float dy = __fsub_rn(p.y, pj.y);
                float s2 = __fadd_rn(__fmul_rn(dx, dx), __fmul_rn(dy, dy));
                d = (s2 > 0.0f) ? __fsqrt_rn(s2) : 0.0f;
            } else {
                d = 1000000000.0f;
            }
            ull key = (((ull)__float_as_uint(d)) << 32) | (unsigned)j;
            #pragma unroll
            for (int q = 0; q < KNBR; q++) {
                if (key < nn[q]) { ull tmp = nn[q]; nn[q] = key; key = tmp; }
            }
        }
    }

    ull res = 0xFFFFFFFFFFFFFFFFULL;
    #pragma unroll
    for (int q = 0; q < KNBR; q++) {
        ull h = nn[0];
        #pragma unroll
        for (int off = 16; off > 0; off >>= 1) {
            ull o = __shfl_xor_sync(0xffffffffu, h, off);
            h = (o < h) ? o : h;
        }
        if (lane == q) res = h;
        if (nn[0] == h) {
            #pragma unroll
            for (int r = 0; r < KNBR-1; r++) nn[r] = nn[r+1];
            nn[KNBR-1] = 0xFFFFFFFFFFFFFFFFULL;
        }
    }

    if (lane < KNBR) {
        const float DIST_T = (float)(4.05 / 4.2);
        unsigned jd = (unsigned)res;
        float d = __uint_as_float((unsigned)(res >> 32));
        bool ev = (d < DIST_T) && (sv != 0);
        float evf = ev ? 1.0f : 0.0f;
        float2 pj = s_xy[jd];
        float dx = __fsub_rn(pj.x, p.x);
        float dy = __fsub_rn(pj.y, p.y);
        float s2 = __fadd_rn(__fmul_rn(dx, dx), __fmul_rn(dy, dy));
        float cd = (s2 > 0.0f) ? __fsqrt_rn(s2) : 0.0f;
        size_t e = ((size_t)b*MAXN + node)*KNBR + lane;
        out[O_EI + e]              = ev ? (float)(b*MAXN + node) : 0.0f;
        out[O_EI + N_EDGE_TOT + e] = ev ? (float)(b*MAXN + jd)   : 0.0f;
        out[O_EF + e*3 + 0] = dx * evf;
        out[O_EF + e*3 + 1] = dy * evf;
        out[O_EF + e*3 + 2] = cd * evf;
        out[O_EV + e] = evf;
    }
}

extern "C" void kernel_launch(void* const* d_in, const int* in_sizes, int n_in,
                              void* d_out, int out_size)
{
    const float* img = (const float*)d_in[0];
    const float* w1  = (const float*)d_in[1];
    const float* w2  = (const float*)d_in[2];
    const float* w3  = (const float*)d_in[3];
    float* out = (float*)d_out;

    const int smemM = 113 * 1024;  // 112,256 B used
    cudaFuncSetAttribute(main_kernel,
                         cudaFuncAttributeMaxDynamicSharedMemorySize, smemM);
    main_kernel<<<B, TC, smemM>>>(img, w1, w2, w3, out);

    nn_kernel<<<dim3(B, (MAXN + TN/32 - 1) / (TN/32)), TN>>>(out);
}